// round 14
// baseline (speedup 1.0000x reference)
#include <cuda_runtime.h>
#include <cuda_bf16.h>

// Shapes: query (N,T,C,L)=(32,64,256,64) fp32; key (T,N,C); out (T,N,C)
#define N_ 32
#define T_ 64
#define C_ 256
#define L_ 64
#define P_THRESH 1e-7f

__device__ float g_part[N_ * T_ * L_];   // per-(n,t) partial scores
__device__ float g_w[N_][L_];            // compact softmax weights
__device__ int   g_idx[N_][L_];          // compact l indices
__device__ int   g_cnt[N_];              // list length per n
__device__ int   g_arrive[N_];           // arrival counter (self-resetting)

// ---------------------------------------------------------------------------
// Kernel 1: partial scores (proven body) + LAST-ARRIVAL softmax epilogue.
// The 64th block of each n (threadFenceReduction pattern: fence + atomic,
// NO waiting) computes softmax over the fully-published partials, compacts
// significant weights, and resets the counter for the next graph replay.
// ---------------------------------------------------------------------------
__global__ __launch_bounds__(256, 6) void k_scores(const float* __restrict__ q,
                                                   const float* __restrict__ key) {
    const int b = blockIdx.x;
    const int n = b >> 6;
    const int t = b & 63;
    const int tid = threadIdx.x;
    const int w = tid >> 5;
    const int lane = tid & 31;
    const int half = lane >> 4;
    const int l4 = lane & 15;

    const float kreg = key[((size_t)t * N_ + n) * C_ + (w << 5) + lane];
    const float4* __restrict__ qb = reinterpret_cast<const float4*>(q);
    const size_t rowbase = (size_t)b * C_;

    float4 acc = make_float4(0.f, 0.f, 0.f, 0.f);
    #pragma unroll
    for (int i = 0; i < 16; ++i) {
        const int r = (i << 1) + half;
        const float kv = __shfl_sync(0xffffffffu, kreg, r);
        const float4 qv = qb[(rowbase + (w << 5) + r) * 16 + l4];
        acc.x = fmaf(kv, qv.x, acc.x);
        acc.y = fmaf(kv, qv.y, acc.y);
        acc.z = fmaf(kv, qv.z, acc.z);
        acc.w = fmaf(kv, qv.w, acc.w);
    }
    acc.x += __shfl_xor_sync(0xffffffffu, acc.x, 16);
    acc.y += __shfl_xor_sync(0xffffffffu, acc.y, 16);
    acc.z += __shfl_xor_sync(0xffffffffu, acc.z, 16);
    acc.w += __shfl_xor_sync(0xffffffffu, acc.w, 16);

    __shared__ float4 sm[8][16];
    if (half == 0) sm[w][l4] = acc;
    __syncthreads();
    if (tid < 16) {
        float4 tot = sm[0][tid];
        #pragma unroll
        for (int j = 1; j < 8; ++j) {
            const float4 v = sm[j][tid];
            tot.x += v.x; tot.y += v.y; tot.z += v.z; tot.w += v.w;
        }
        reinterpret_cast<float4*>(g_part + (size_t)b * L_)[tid] = tot;
    }

    // ---- last-arrival epilogue (no waiting) ----
    __threadfence();
    __syncthreads();
    __shared__ int s_last;
    if (tid == 0) s_last = (atomicAdd(&g_arrive[n], 1) == T_ - 1);
    __syncthreads();
    if (!s_last) return;

    // This block saw all 64 partials published: softmax + compaction for n.
    __shared__ float s_red[4];
    __shared__ int   wcnt[2];
    float s = 0.f, e = 0.f;
    const int w2 = tid >> 5;
    if (tid < L_) {
        const float* __restrict__ p = g_part + (size_t)n * T_ * L_ + tid;
        #pragma unroll
        for (int t2 = 0; t2 < T_; ++t2) s += p[t2 * L_];
        float m = s;
        #pragma unroll
        for (int off = 16; off; off >>= 1)
            m = fmaxf(m, __shfl_xor_sync(0xffffffffu, m, off));
        if (lane == 0) s_red[w2] = m;
    }
    __syncthreads();
    if (tid < L_) {
        const float m = fmaxf(s_red[0], s_red[1]);
        e = __expf(s - m);
        float sum = e;
        #pragma unroll
        for (int off = 16; off; off >>= 1)
            sum += __shfl_xor_sync(0xffffffffu, sum, off);
        if (lane == 0) s_red[2 + w2] = sum;
    }
    __syncthreads();
    if (tid < L_) {
        const float prob = e / (s_red[2] + s_red[3]);
        const bool keep = prob > P_THRESH;
        const unsigned mask = __ballot_sync(0xffffffffu, keep);
        const int prefix = __popc(mask & ((1u << lane) - 1u));
        if (lane == 0) wcnt[w2] = __popc(mask);
        __syncwarp();
        // cross-warp base needs both counts: barrier below covers it
    }
    __syncthreads();
    if (tid < L_) {
        const float prob = e / (s_red[2] + s_red[3]);
        const bool keep = prob > P_THRESH;
        const unsigned mask = __ballot_sync(0xffffffffu, keep);
        const int prefix = __popc(mask & ((1u << lane) - 1u));
        const int base = (w2 == 1) ? wcnt[0] : 0;
        if (keep) {
            g_w[n][base + prefix] = prob;
            g_idx[n][base + prefix] = tid;
        }
        if (tid == 0) g_cnt[n] = wcnt[0] + wcnt[1];
    }
    __syncthreads();
    if (tid == 0) g_arrive[n] = 0;   // reset for next graph replay
}

// ---------------------------------------------------------------------------
// Kernel 2: pure sparse gather. Per-n compact list is tiny + L2-broadcast;
// each thread issues its scattered load(s) immediately (cnt is usually 1).
// ---------------------------------------------------------------------------
__global__ __launch_bounds__(256) void k_gather(const float* __restrict__ q,
                                                float* __restrict__ out) {
    const int b = blockIdx.x;
    const int n = b >> 6;
    const int t = b & 63;
    const int c = threadIdx.x;

    const int m = g_cnt[n];
    const float* __restrict__ qrow = q + ((size_t)b * C_ + c) * L_;

    float acc = 0.f;
    #pragma unroll 2
    for (int j = 0; j < m; ++j)
        acc = fmaf(g_w[n][j], __ldg(qrow + g_idx[n][j]), acc);

    out[((size_t)t * N_ + n) * C_ + c] = acc;
}

extern "C" void kernel_launch(void* const* d_in, const int* in_sizes, int n_in,
                              void* d_out, int out_size) {
    const float* q   = (const float*)d_in[0];
    const float* key = (const float*)d_in[1];
    float* out = (float*)d_out;

    k_scores<<<N_ * T_, 256>>>(q, key);
    k_gather<<<N_ * T_, 256>>>(q, out);
}

// round 15
// speedup vs baseline: 1.0855x; 1.0855x over previous
#include <cuda_runtime.h>
#include <cuda_bf16.h>

// Shapes: query (N,T,C,L)=(32,64,256,64) fp32; key (T,N,C); out (T,N,C)
#define N_ 32
#define T_ 64
#define C_ 256
#define L_ 64
#define P_THRESH 1e-7f

__device__ float g_part[N_ * T_ * L_];   // per-(n,t) partial scores

// ---------------------------------------------------------------------------
// Kernel 1: partial scores (unchanged proven body, 24.4us @ 72.5% DRAM).
// Streams q front-to-back -> q's TAIL ends L2-resident.
// ---------------------------------------------------------------------------
__global__ __launch_bounds__(256, 6) void k_scores(const float* __restrict__ q,
                                                   const float* __restrict__ key) {
    const int b = blockIdx.x;
    const int n = b >> 6;
    const int t = b & 63;
    const int w = threadIdx.x >> 5;
    const int lane = threadIdx.x & 31;
    const int half = lane >> 4;
    const int l4 = lane & 15;

    const float kreg = key[((size_t)t * N_ + n) * C_ + (w << 5) + lane];
    const float4* __restrict__ qb = reinterpret_cast<const float4*>(q);
    const size_t rowbase = (size_t)b * C_;

    float4 acc = make_float4(0.f, 0.f, 0.f, 0.f);
    #pragma unroll
    for (int i = 0; i < 16; ++i) {
        const int r = (i << 1) + half;
        const float kv = __shfl_sync(0xffffffffu, kreg, r);
        const float4 qv = qb[(rowbase + (w << 5) + r) * 16 + l4];
        acc.x = fmaf(kv, qv.x, acc.x);
        acc.y = fmaf(kv, qv.y, acc.y);
        acc.z = fmaf(kv, qv.z, acc.z);
        acc.w = fmaf(kv, qv.w, acc.w);
    }
    acc.x += __shfl_xor_sync(0xffffffffu, acc.x, 16);
    acc.y += __shfl_xor_sync(0xffffffffu, acc.y, 16);
    acc.z += __shfl_xor_sync(0xffffffffu, acc.z, 16);
    acc.w += __shfl_xor_sync(0xffffffffu, acc.w, 16);

    __shared__ float4 sm[8][16];
    if (half == 0) sm[w][l4] = acc;
    __syncthreads();
    if (threadIdx.x < 16) {
        float4 tot = sm[0][threadIdx.x];
        #pragma unroll
        for (int j = 1; j < 8; ++j) {
            const float4 v = sm[j][threadIdx.x];
            tot.x += v.x; tot.y += v.y; tot.z += v.z; tot.w += v.w;
        }
        reinterpret_cast<float4*>(g_part + (size_t)b * L_)[threadIdx.x] = tot;
    }
}

// ---------------------------------------------------------------------------
// Kernel 2 (fused, REVERSED): block mapping runs tail-first so the sparse
// gather's scattered reads hit the L2-resident tail of q left by k_scores
// (the gather's 4B reads amplify to full line fills -> L2 hits are the win).
// Redundant per-block softmax from g_part (L2-hot), compaction in smem,
// then sparse gather. Same proven R12 body otherwise.
// ---------------------------------------------------------------------------
__global__ __launch_bounds__(256) void k_sg(const float* __restrict__ q,
                                            float* __restrict__ out) {
    const int b = (N_ * T_ - 1) - blockIdx.x;   // REVERSED for L2 reuse
    const int n = b >> 6;
    const int t = b & 63;
    const int tid = threadIdx.x;
    const int lane = tid & 31;

    __shared__ float s_part[4][L_];
    __shared__ float s_w[L_];
    __shared__ int   s_idx[L_];
    __shared__ int   s_cnt;
    __shared__ float s_red[4];

    // ---- phase 1: sum partials over t, 4-way split, coalesced over l ----
    {
        const int l = tid & 63;
        const int tp = tid >> 6;               // 4 groups x 16 t's
        float s = 0.f;
        const float* __restrict__ p =
            g_part + ((size_t)n * T_ + tp * 16) * L_ + l;
        #pragma unroll
        for (int tt = 0; tt < 16; ++tt) s += p[tt * L_];
        s_part[tp][l] = s;
    }
    __syncthreads();

    // ---- phase 2: softmax + compaction (threads 0..63) ----
    if (tid < L_) {
        const int w2 = tid >> 5;
        float s = s_part[0][tid] + s_part[1][tid]
                + s_part[2][tid] + s_part[3][tid];

        float m = s;
        #pragma unroll
        for (int off = 16; off; off >>= 1)
            m = fmaxf(m, __shfl_xor_sync(0xffffffffu, m, off));
        if (lane == 0) s_red[w2] = m;
        __syncwarp();
        __syncthreads();
        m = fmaxf(s_red[0], s_red[1]);

        const float e = __expf(s - m);
        float sum = e;
        #pragma unroll
        for (int off = 16; off; off >>= 1)
            sum += __shfl_xor_sync(0xffffffffu, sum, off);
        if (lane == 0) s_red[2 + w2] = sum;
        __syncthreads();
        const float prob = e / (s_red[2] + s_red[3]);

        // deterministic compaction of significant weights
        const bool keep = prob > P_THRESH;
        const unsigned mask = __ballot_sync(0xffffffffu, keep);
        const int prefix = __popc(mask & ((1u << lane) - 1u));
        __shared__ int wcnt[2];
        if (lane == 0) wcnt[w2] = __popc(mask);
        __syncthreads();
        const int base = (w2 == 1) ? wcnt[0] : 0;
        if (keep) {
            s_w[base + prefix] = prob;
            s_idx[base + prefix] = tid;
        }
        if (tid == 0) s_cnt = wcnt[0] + wcnt[1];
    } else {
        __syncthreads();   // match phase-2 barriers
        __syncthreads();
        __syncthreads();
    }
    __syncthreads();

    // ---- phase 3: sparse gather (thread tid == c) ----
    const int cnt = s_cnt;
    const float* __restrict__ qrow = q + ((size_t)b * C_ + tid) * L_;
    float acc = 0.f;
    for (int j = 0; j < cnt; ++j)
        acc = fmaf(s_w[j], __ldg(qrow + s_idx[j]), acc);

    out[((size_t)t * N_ + n) * C_ + tid] = acc;
}

extern "C" void kernel_launch(void* const* d_in, const int* in_sizes, int n_in,
                              void* d_out, int out_size) {
    const float* q   = (const float*)d_in[0];
    const float* key = (const float*)d_in[1];
    float* out = (float*)d_out;

    k_scores<<<N_ * T_, 256>>>(q, key);
    k_sg<<<N_ * T_, 256>>>(q, out);
}